// round 10
// baseline (speedup 1.0000x reference)
#include <cuda_runtime.h>
#include <cuda_bf16.h>
#include <cstdint>

#define NQ 6
#define BATCH 256

__device__ float g_C[2 * 729];
__device__ int g_flag;   // adjoint-done counter (0 -> 2), reset each launch
__device__ int g_done;   // encoder-done counter (0 -> 64), reset each launch

#define L1F 0.99866666666666666f   /* 1 - 4*0.001/3 */
#define L12F 0.98535111111111111f  /* L1 * (1 - 4*0.01/3) */

// bank-conflict swizzle for the 4096-entry Pauli table (GF(2)-linear)
#define SW(i) ((i) ^ (((i) >> 5) & 31))

// ---------- adjoint (Heisenberg) Pauli-basis sweeps; symplectic digits I=0,X=1,Z=2,Y=3 ----------

template<bool CTRL_A>
__device__ __forceinline__ void cnot_regs(float v[4][4]) {
    float w[4][4];
#pragma unroll
    for (int da = 0; da < 4; da++)
#pragma unroll
        for (int db = 0; db < 4; db++) {
            int dc = CTRL_A ? da : db;
            int dt = CTRL_A ? db : da;
            int xc = dc & 1, zc = dc >> 1, xt = dt & 1, zt = dt >> 1;
            int ndc = xc | ((zc ^ zt) << 1);
            int ndt = (xt ^ xc) | (zt << 1);
            int na = CTRL_A ? ndc : ndt;
            int nb = CTRL_A ? ndt : ndc;
            int neg = xc & zt & (1 ^ (zc ^ xt));
            float val = v[da][db];
            w[na][nb] = neg ? -val : val;
        }
#pragma unroll
    for (int i = 0; i < 4; i++)
#pragma unroll
        for (int j = 0; j < 4; j++) v[i][j] = w[i][j];
}

// Byte offsets: 4*SW(base+off) = tb ^ (4*SW(off)), tb = 4*SW(base); integer-space XOR is exact.
template<int A, int B, bool CTRL_B1, bool DOUBLE, bool DEPOL, bool RA, bool RB>
__device__ __forceinline__ void sweep(float* T, const float* Ma, const float* Mb, int tid) {
    __syncthreads();
    constexpr int lo = 2 * A, hi = 2 * B;
    int m1 = (1 << lo) - 1;
    int t1 = ((tid & ~m1) << 2) | (tid & m1);
    int m2 = (1 << hi) - 1;
    int base = ((t1 & ~m2) << 2) | (t1 & m2);
    int tb = 4 * SW(base);
    char* Tc = (char*)T;

    float v[4][4];
#pragma unroll
    for (int i = 0; i < 4; i++)
#pragma unroll
        for (int j = 0; j < 4; j++) {
            int off = (i << lo) | (j << hi);
            int c4 = 4 * SW(off);
            v[i][j] = *(const float*)(Tc + (tb ^ c4));
        }

    if (DEPOL) {
        float fixed = 1.f;
#pragma unroll
        for (int q = 0; q < 6; q++) {
            if (q == A || q == B) continue;
            if ((base >> (2 * q)) & 3) fixed *= (q == 5 ? L1F : L12F);
        }
        const float la = (A == 5 ? L1F : L12F), lb = (B == 5 ? L1F : L12F);
#pragma unroll
        for (int i = 0; i < 4; i++)
#pragma unroll
            for (int j = 0; j < 4; j++) {
                float f = fixed;
                if (i) f *= la;
                if (j) f *= lb;
                v[i][j] *= f;
            }
    }

    cnot_regs<!CTRL_B1>(v);
    if (DOUBLE) cnot_regs<CTRL_B1>(v);

    if (RA) {
        float a0 = Ma[0], a1 = Ma[1], a2 = Ma[2], a3 = Ma[3], a4 = Ma[4];
        float a5 = Ma[5], a6 = Ma[6], a7 = Ma[7], a8 = Ma[8];
#pragma unroll
        for (int j = 0; j < 4; j++) {
            float x = v[1][j], z = v[2][j], y = v[3][j];
            v[1][j] = fmaf(a0, x, fmaf(a1, z, a2 * y));
            v[2][j] = fmaf(a3, x, fmaf(a4, z, a5 * y));
            v[3][j] = fmaf(a6, x, fmaf(a7, z, a8 * y));
        }
    }
    if (RB) {
        float b0 = Mb[0], b1 = Mb[1], b2 = Mb[2], b3 = Mb[3], b4 = Mb[4];
        float b5 = Mb[5], b6 = Mb[6], b7 = Mb[7], b8 = Mb[8];
#pragma unroll
        for (int i = 0; i < 4; i++) {
            float x = v[i][1], z = v[i][2], y = v[i][3];
            v[i][1] = fmaf(b0, x, fmaf(b1, z, b2 * y));
            v[i][2] = fmaf(b3, x, fmaf(b4, z, b5 * y));
            v[i][3] = fmaf(b6, x, fmaf(b7, z, b8 * y));
        }
    }

#pragma unroll
    for (int i = 0; i < 4; i++)
#pragma unroll
        for (int j = 0; j < 4; j++) {
            int off = (i << lo) | (j << hi);
            int c4 = 4 * SW(off);
            *(float*)(Tc + (tb ^ c4)) = v[i][j];
        }
}

__device__ __forceinline__ void layerR1(float* T, const float* M, int tid) {
    sweep<0, 5, true,  false, false, false, false>(T, M, M, tid);                  // C(5,0)
    sweep<4, 5, false, false, false, false, true >(T, M, M + 5 * 9, tid);          // C(4,5), R5
    sweep<3, 4, false, false, false, false, true >(T, M, M + 4 * 9, tid);          // C(3,4), R4
    sweep<2, 3, false, false, false, false, true >(T, M, M + 3 * 9, tid);          // C(2,3), R3
    sweep<1, 2, false, false, false, false, true >(T, M, M + 2 * 9, tid);          // C(1,2), R2
    sweep<0, 1, false, false, false, true,  true >(T, M + 0 * 9, M + 1 * 9, tid);  // C(0,1), R0, R1
}

__device__ __forceinline__ void layerR2(float* T, const float* M, int tid) {
    sweep<1, 5, true,  false, false, false, false>(T, M, M, tid);                  // C(5,1)
    sweep<3, 5, false, false, false, false, true >(T, M, M + 5 * 9, tid);          // C(3,5), R5
    sweep<1, 3, false, false, false, true,  true >(T, M + 1 * 9, M + 3 * 9, tid);  // C(1,3), R1, R3
    sweep<0, 4, true,  false, false, false, false>(T, M, M, tid);                  // C(4,0)
    sweep<2, 4, false, false, false, false, true >(T, M, M + 4 * 9, tid);          // C(2,4), R4
    sweep<0, 2, false, false, false, true,  true >(T, M + 0 * 9, M + 2 * 9, tid);  // C(0,2), R0, R2
}

__device__ __forceinline__ void layerR3(float* T, const float* M, int tid) {
    sweep<2, 5, true, true, true,  true, true>(T, M + 2 * 9, M + 5 * 9, tid);  // depol, C(5,2), C(2,5), R2, R5
    sweep<1, 4, true, true, false, true, true>(T, M + 1 * 9, M + 4 * 9, tid);  // C(4,1), C(1,4), R1, R4
    sweep<0, 3, true, true, false, true, true>(T, M + 0 * 9, M + 3 * 9, tid);  // C(3,0), C(0,3), R0, R3
}

// ---------------- single fused kernel ----------------
// blocks 0..63: encoder (4 batch rows) -> spin on g_flag -> contract -> out
// blocks 64,65: adjoint Heisenberg evolution -> g_C -> bump g_flag
__global__ __launch_bounds__(256) void fused_all_kernel(
    const float* __restrict__ x, const float* __restrict__ W1, const float* __restrict__ b1,
    const float* __restrict__ ln_g, const float* __restrict__ ln_b,
    const float* __restrict__ W2, const float* __restrict__ b2,
    const float* __restrict__ shared_w, const float* __restrict__ task_w,
    const float* __restrict__ Wp, const float* __restrict__ bp,
    float* __restrict__ out)
{
    __shared__ __align__(16) float SM[4416];
    int tid = threadIdx.x;
    int lane = tid & 31, warp = tid >> 5;

    if (blockIdx.x < 64) {
        // ======== encoder: 4 batch rows per block, coalesced W1 with prefetch ========
        int b0 = blockIdx.x * 4;
        float* hs = SM;              // [4][256]
        float* red = SM + 1024;      // 32
        float* stat = SM + 1056;     // 4
        float* stat2 = SM + 1060;    // 4
        float* zs = SM + 1064;       // [4][6]
        float* u = SM + 1088;        // [4][3][9] = 108
        float* cred = SM + 1196;     // [8][2]

        float4 xr[4][6];
        float xt[4];
#pragma unroll
        for (int r = 0; r < 4; r++) {
            const float4* xg = (const float4*)(x + (size_t)(b0 + r) * 784);
#pragma unroll
            for (int i = 0; i < 6; i++) xr[r][i] = xg[lane + 32 * i];
            xt[r] = (lane < 16) ? x[(size_t)(b0 + r) * 784 + 768 + lane] : 0.f;
        }

        // preload W1 row warp*32
        float4 wr[6];
        float wt;
        {
            const float4* wg = (const float4*)(W1 + (size_t)(warp * 32) * 784);
#pragma unroll
            for (int i = 0; i < 6; i++) wr[i] = wg[lane + 32 * i];
            wt = (lane < 16) ? W1[(size_t)(warp * 32) * 784 + 768 + lane] : 0.f;
        }

        for (int j = 0; j < 32; j++) {
            int row = warp * 32 + j;
            // prefetch next row before consuming current one
            float4 wn[6];
            float wtn = 0.f;
            if (j < 31) {
                const float4* wg = (const float4*)(W1 + (size_t)(row + 1) * 784);
#pragma unroll
                for (int i = 0; i < 6; i++) wn[i] = wg[lane + 32 * i];
                wtn = (lane < 16) ? W1[(size_t)(row + 1) * 784 + 768 + lane] : 0.f;
            }
            float a0 = 0.f, a1 = 0.f, a2 = 0.f, a3 = 0.f;
#pragma unroll
            for (int i = 0; i < 6; i++) {
                float4 w4 = wr[i];
                a0 = fmaf(w4.x, xr[0][i].x, fmaf(w4.y, xr[0][i].y, fmaf(w4.z, xr[0][i].z, fmaf(w4.w, xr[0][i].w, a0))));
                a1 = fmaf(w4.x, xr[1][i].x, fmaf(w4.y, xr[1][i].y, fmaf(w4.z, xr[1][i].z, fmaf(w4.w, xr[1][i].w, a1))));
                a2 = fmaf(w4.x, xr[2][i].x, fmaf(w4.y, xr[2][i].y, fmaf(w4.z, xr[2][i].z, fmaf(w4.w, xr[2][i].w, a2))));
                a3 = fmaf(w4.x, xr[3][i].x, fmaf(w4.y, xr[3][i].y, fmaf(w4.z, xr[3][i].z, fmaf(w4.w, xr[3][i].w, a3))));
            }
            a0 = fmaf(wt, xt[0], a0);
            a1 = fmaf(wt, xt[1], a1);
            a2 = fmaf(wt, xt[2], a2);
            a3 = fmaf(wt, xt[3], a3);
#pragma unroll
            for (int o = 16; o > 0; o >>= 1) {
                a0 += __shfl_xor_sync(0xffffffffu, a0, o);
                a1 += __shfl_xor_sync(0xffffffffu, a1, o);
                a2 += __shfl_xor_sync(0xffffffffu, a2, o);
                a3 += __shfl_xor_sync(0xffffffffu, a3, o);
            }
            if (lane == 0) {
                float bv = b1[row];
                hs[row] = fmaxf(a0 + bv, 0.f);
                hs[256 + row] = fmaxf(a1 + bv, 0.f);
                hs[512 + row] = fmaxf(a2 + bv, 0.f);
                hs[768 + row] = fmaxf(a3 + bv, 0.f);
            }
#pragma unroll
            for (int i = 0; i < 6; i++) wr[i] = wn[i];
            wt = wtn;
        }
        __syncthreads();

        float h0 = hs[tid], h1 = hs[256 + tid], h2 = hs[512 + tid], h3 = hs[768 + tid];
        {
            float t0 = h0, t1 = h1, t2 = h2, t3 = h3;
#pragma unroll
            for (int o = 16; o > 0; o >>= 1) {
                t0 += __shfl_xor_sync(0xffffffffu, t0, o);
                t1 += __shfl_xor_sync(0xffffffffu, t1, o);
                t2 += __shfl_xor_sync(0xffffffffu, t2, o);
                t3 += __shfl_xor_sync(0xffffffffu, t3, o);
            }
            if (lane == 0) { red[warp] = t0; red[8 + warp] = t1; red[16 + warp] = t2; red[24 + warp] = t3; }
        }
        __syncthreads();
        if (tid < 4) {
            float s = 0.f;
#pragma unroll
            for (int w = 0; w < 8; w++) s += red[tid * 8 + w];
            stat[tid] = s * (1.f / 256.f);
        }
        __syncthreads();
        float d0 = h0 - stat[0], d1 = h1 - stat[1], d2 = h2 - stat[2], d3 = h3 - stat[3];
        {
            float t0 = d0 * d0, t1 = d1 * d1, t2 = d2 * d2, t3 = d3 * d3;
#pragma unroll
            for (int o = 16; o > 0; o >>= 1) {
                t0 += __shfl_xor_sync(0xffffffffu, t0, o);
                t1 += __shfl_xor_sync(0xffffffffu, t1, o);
                t2 += __shfl_xor_sync(0xffffffffu, t2, o);
                t3 += __shfl_xor_sync(0xffffffffu, t3, o);
            }
            if (lane == 0) { red[warp] = t0; red[8 + warp] = t1; red[16 + warp] = t2; red[24 + warp] = t3; }
        }
        __syncthreads();
        if (tid < 4) {
            float s = 0.f;
#pragma unroll
            for (int w = 0; w < 8; w++) s += red[tid * 8 + w];
            stat2[tid] = rsqrtf(s * (1.f / 256.f) + 1e-5f);
        }
        __syncthreads();
        float g = ln_g[tid], be = ln_b[tid];
        hs[tid] = fmaf(d0 * stat2[0], g, be);
        hs[256 + tid] = fmaf(d1 * stat2[1], g, be);
        hs[512 + tid] = fmaf(d2 * stat2[2], g, be);
        hs[768 + tid] = fmaf(d3 * stat2[3], g, be);
        __syncthreads();

        // z = tanh(h @ W2^T + b2) -> smem zs
        for (int p = warp; p < 24; p += 8) {
            int r = p / 6, j = p - r * 6;
            const float* hr = hs + r * 256;
            const float* wj = W2 + j * 256;
            float s = 0.f;
#pragma unroll
            for (int t2_ = lane; t2_ < 256; t2_ += 32) s = fmaf(hr[t2_], wj[t2_], s);
#pragma unroll
            for (int o = 16; o > 0; o >>= 1) s += __shfl_xor_sync(0xffffffffu, s, o);
            if (lane == 0) zs[r * 6 + j] = tanhf(s + b2[j]);
        }

        // ---- wait for adjoint blocks (g_C ready) ----
        if (tid == 0) {
            while (*(volatile int*)&g_flag < 2) { }
        }
        __syncthreads();
        __threadfence();

        // ---- contraction for this block's 4 rows ----
        if (tid < 108) {
            int r = tid / 27, rem = tid % 27, p = rem / 9, ij = rem % 9;
            int i = ij % 3, jj = ij / 3;
            float sa, ca, sb, cb;
            __sincosf(3.14159265358979323846f * zs[r * 6 + 2 * p], &sa, &ca);
            __sincosf(3.14159265358979323846f * zs[r * 6 + 2 * p + 1], &sb, &cb);
            float vi = (i == 0) ? 1.f : ((i == 1) ? L1F * sa : L1F * ca);
            float vj = (jj == 0) ? 1.f : ((jj == 1) ? L1F * sb : L1F * cb);
            u[r * 27 + p * 9 + ij] = vi * vj;
        }
        __syncthreads();

        {
            int r = warp >> 1;                 // warp pair handles row r
            const float* ur = u + r * 27;
            float acc0 = 0.f, acc1 = 0.f;
            for (int s = lane + 32 * (warp & 1); s < 729; s += 64) {
                int i01 = s % 9, q9 = s / 9;
                int i23 = q9 % 9, i45 = q9 / 9;
                float w = ur[i01] * ur[9 + i23] * ur[18 + i45];
                acc0 = fmaf(g_C[s], w, acc0);
                acc1 = fmaf(g_C[729 + s], w, acc1);
            }
#pragma unroll
            for (int o = 16; o > 0; o >>= 1) {
                acc0 += __shfl_xor_sync(0xffffffffu, acc0, o);
                acc1 += __shfl_xor_sync(0xffffffffu, acc1, o);
            }
            if (lane == 0) { cred[warp * 2] = acc0; cred[warp * 2 + 1] = acc1; }
        }
        __syncthreads();
        if (tid < 8) {
            int r = tid >> 1, o = tid & 1;
            out[(b0 + r) * 2 + o] = cred[(2 * r) * 2 + o] + cred[(2 * r + 1) * 2 + o] + bp[o];
        }
        __syncthreads();
        // self-resetting barrier state (last of the 64 encoder blocks resets)
        if (tid == 0) {
            int v = atomicAdd(&g_done, 1);
            if (v == 63) { g_done = 0; g_flag = 0; }
        }
    } else {
        // ======== adjoint Heisenberg evolution for O_op = sum_i Wp[op,i] Z_i ========
        int op = blockIdx.x - 64;
        float* T = SM;            // 4096 Pauli coefficients (swizzled)
        float* MA = SM + 4096;    // 30 x 9 adjoint Bloch matrices (XZY basis)

        if (tid < 30) {
            const float* w = (tid < 18) ? (shared_w + tid * 3) : (task_w + (tid - 18) * 3);
            float a = -w[0], b = -w[1], gg = -w[2];
            float ca, sa, cb, sb, cg, sg;
            sincosf(a, &sa, &ca);
            sincosf(b, &sb, &cb);
            sincosf(gg, &sg, &cg);
            float A00 = ca * cb * cg - sa * sg;
            float A01 = -ca * cb * sg - sa * cg;
            float A02 = ca * sb;
            float A10 = sa * cb * cg + ca * sg;
            float A11 = -sa * cb * sg + ca * cg;
            float A12 = sa * sb;
            float A20 = -sb * cg;
            float A21 = sb * sg;
            float A22 = cb;
            float* M = MA + tid * 9;   // order (X,Z,Y) = XYZ rows/cols (0,2,1)
            M[0] = A00; M[1] = A02; M[2] = A01;
            M[3] = A20; M[4] = A22; M[5] = A21;
            M[6] = A10; M[7] = A12; M[8] = A11;
        }
#pragma unroll
        for (int k = 0; k < 16; k++) T[tid + 256 * k] = 0.f;
        __syncthreads();
        if (tid < 6) T[SW(2 << (2 * tid))] = L1F * Wp[op * NQ + tid];

        for (int it = 0; it < 2; it++) {
            layerR2(T, MA + (it ? 6 : 24) * 9, tid);
            layerR1(T, MA + (it ? 0 : 18) * 9, tid);
            if (it == 0) layerR3(T, MA + 12 * 9, tid);
        }
        __syncthreads();
        // write Y-free strings compacted to base-3 index
#pragma unroll
        for (int k = 0; k < 16; k++) {
            int s = tid + 256 * k;
            if ((s & (s >> 1) & 0x555) == 0) {
                int s3 = 0;
#pragma unroll
                for (int q = 5; q >= 0; q--) s3 = s3 * 3 + ((s >> (2 * q)) & 3);
                g_C[op * 729 + s3] = T[SW(s)];
            }
        }
        __threadfence();
        __syncthreads();
        if (tid == 0) atomicAdd(&g_flag, 1);
    }
}

extern "C" void kernel_launch(void* const* d_in, const int* in_sizes, int n_in,
                              void* d_out, int out_size) {
    const float* x        = (const float*)d_in[0];
    const float* W1       = (const float*)d_in[1];
    const float* b1       = (const float*)d_in[2];
    const float* ln_g     = (const float*)d_in[3];
    const float* ln_b     = (const float*)d_in[4];
    const float* W2       = (const float*)d_in[5];
    const float* b2       = (const float*)d_in[6];
    const float* shared_w = (const float*)d_in[7];
    const float* task_w   = (const float*)d_in[8];
    const float* Wp       = (const float*)d_in[9];
    const float* bp       = (const float*)d_in[10];
    float* out = (float*)d_out;

    fused_all_kernel<<<66, 256>>>(x, W1, b1, ln_g, ln_b, W2, b2,
                                  shared_w, task_w, Wp, bp, out);
}

// round 12
// speedup vs baseline: 1.0014x; 1.0014x over previous
#include <cuda_runtime.h>
#include <cuda_bf16.h>
#include <cstdint>

#define NQ 6
#define BATCH 256

__device__ float g_C[2 * 729];
__device__ int g_flag;   // adjoint-done counter (0 -> 2), reset each launch
__device__ int g_done;   // encoder-done counter (0 -> 64), reset each launch

#define L1F 0.99866666666666666f   /* 1 - 4*0.001/3 */
#define L12F 0.98535111111111111f  /* L1 * (1 - 4*0.01/3) */

// bank-conflict swizzle for the 4096-entry Pauli table (GF(2)-linear)
#define SW(i) ((i) ^ (((i) >> 5) & 31))

typedef unsigned long long u64;

// packed dual-fp32 FMA (sm_100+): d = a*b + c elementwise on two lanes
__device__ __forceinline__ u64 ffma2(u64 a, u64 b, u64 c) {
    u64 d;
    asm("fma.rn.f32x2 %0, %1, %2, %3;" : "=l"(d) : "l"(a), "l"(b), "l"(c));
    return d;
}

// ---------- adjoint (Heisenberg) Pauli-basis sweeps; symplectic digits I=0,X=1,Z=2,Y=3 ----------

template<bool CTRL_A>
__device__ __forceinline__ void cnot_regs(float v[4][4]) {
    float w[4][4];
#pragma unroll
    for (int da = 0; da < 4; da++)
#pragma unroll
        for (int db = 0; db < 4; db++) {
            int dc = CTRL_A ? da : db;
            int dt = CTRL_A ? db : da;
            int xc = dc & 1, zc = dc >> 1, xt = dt & 1, zt = dt >> 1;
            int ndc = xc | ((zc ^ zt) << 1);
            int ndt = (xt ^ xc) | (zt << 1);
            int na = CTRL_A ? ndc : ndt;
            int nb = CTRL_A ? ndt : ndc;
            int neg = xc & zt & (1 ^ (zc ^ xt));
            float val = v[da][db];
            w[na][nb] = neg ? -val : val;
        }
#pragma unroll
    for (int i = 0; i < 4; i++)
#pragma unroll
        for (int j = 0; j < 4; j++) v[i][j] = w[i][j];
}

// Byte offsets: 4*SW(base+off) = tb ^ (4*SW(off)), tb = 4*SW(base); integer-space XOR is exact.
template<int A, int B, bool CTRL_B1, bool DOUBLE, bool DEPOL, bool RA, bool RB>
__device__ __forceinline__ void sweep(float* T, const float* Ma, const float* Mb, int tid) {
    __syncthreads();
    constexpr int lo = 2 * A, hi = 2 * B;
    int m1 = (1 << lo) - 1;
    int t1 = ((tid & ~m1) << 2) | (tid & m1);
    int m2 = (1 << hi) - 1;
    int base = ((t1 & ~m2) << 2) | (t1 & m2);
    int tb = 4 * SW(base);
    char* Tc = (char*)T;

    float v[4][4];
#pragma unroll
    for (int i = 0; i < 4; i++)
#pragma unroll
        for (int j = 0; j < 4; j++) {
            int off = (i << lo) | (j << hi);
            int c4 = 4 * SW(off);
            v[i][j] = *(const float*)(Tc + (tb ^ c4));
        }

    if (DEPOL) {
        float fixed = 1.f;
#pragma unroll
        for (int q = 0; q < 6; q++) {
            if (q == A || q == B) continue;
            if ((base >> (2 * q)) & 3) fixed *= (q == 5 ? L1F : L12F);
        }
        const float la = (A == 5 ? L1F : L12F), lb = (B == 5 ? L1F : L12F);
#pragma unroll
        for (int i = 0; i < 4; i++)
#pragma unroll
            for (int j = 0; j < 4; j++) {
                float f = fixed;
                if (i) f *= la;
                if (j) f *= lb;
                v[i][j] *= f;
            }
    }

    cnot_regs<!CTRL_B1>(v);
    if (DOUBLE) cnot_regs<CTRL_B1>(v);

    if (RA) {
        float a0 = Ma[0], a1 = Ma[1], a2 = Ma[2], a3 = Ma[3], a4 = Ma[4];
        float a5 = Ma[5], a6 = Ma[6], a7 = Ma[7], a8 = Ma[8];
#pragma unroll
        for (int j = 0; j < 4; j++) {
            float x = v[1][j], z = v[2][j], y = v[3][j];
            v[1][j] = fmaf(a0, x, fmaf(a1, z, a2 * y));
            v[2][j] = fmaf(a3, x, fmaf(a4, z, a5 * y));
            v[3][j] = fmaf(a6, x, fmaf(a7, z, a8 * y));
        }
    }
    if (RB) {
        float b0 = Mb[0], b1 = Mb[1], b2 = Mb[2], b3 = Mb[3], b4 = Mb[4];
        float b5 = Mb[5], b6 = Mb[6], b7 = Mb[7], b8 = Mb[8];
#pragma unroll
        for (int i = 0; i < 4; i++) {
            float x = v[i][1], z = v[i][2], y = v[i][3];
            v[i][1] = fmaf(b0, x, fmaf(b1, z, b2 * y));
            v[i][2] = fmaf(b3, x, fmaf(b4, z, b5 * y));
            v[i][3] = fmaf(b6, x, fmaf(b7, z, b8 * y));
        }
    }

#pragma unroll
    for (int i = 0; i < 4; i++)
#pragma unroll
        for (int j = 0; j < 4; j++) {
            int off = (i << lo) | (j << hi);
            int c4 = 4 * SW(off);
            *(float*)(Tc + (tb ^ c4)) = v[i][j];
        }
}

__device__ __forceinline__ void layerR1(float* T, const float* M, int tid) {
    sweep<0, 5, true,  false, false, false, false>(T, M, M, tid);                  // C(5,0)
    sweep<4, 5, false, false, false, false, true >(T, M, M + 5 * 9, tid);          // C(4,5), R5
    sweep<3, 4, false, false, false, false, true >(T, M, M + 4 * 9, tid);          // C(3,4), R4
    sweep<2, 3, false, false, false, false, true >(T, M, M + 3 * 9, tid);          // C(2,3), R3
    sweep<1, 2, false, false, false, false, true >(T, M, M + 2 * 9, tid);          // C(1,2), R2
    sweep<0, 1, false, false, false, true,  true >(T, M + 0 * 9, M + 1 * 9, tid);  // C(0,1), R0, R1
}

__device__ __forceinline__ void layerR2(float* T, const float* M, int tid) {
    sweep<1, 5, true,  false, false, false, false>(T, M, M, tid);                  // C(5,1)
    sweep<3, 5, false, false, false, false, true >(T, M, M + 5 * 9, tid);          // C(3,5), R5
    sweep<1, 3, false, false, false, true,  true >(T, M + 1 * 9, M + 3 * 9, tid);  // C(1,3), R1, R3
    sweep<0, 4, true,  false, false, false, false>(T, M, M, tid);                  // C(4,0)
    sweep<2, 4, false, false, false, false, true >(T, M, M + 4 * 9, tid);          // C(2,4), R4
    sweep<0, 2, false, false, false, true,  true >(T, M + 0 * 9, M + 2 * 9, tid);  // C(0,2), R0, R2
}

__device__ __forceinline__ void layerR3(float* T, const float* M, int tid) {
    sweep<2, 5, true, true, true,  true, true>(T, M + 2 * 9, M + 5 * 9, tid);  // depol, C(5,2), C(2,5), R2, R5
    sweep<1, 4, true, true, false, true, true>(T, M + 1 * 9, M + 4 * 9, tid);  // C(4,1), C(1,4), R1, R4
    sweep<0, 3, true, true, false, true, true>(T, M + 0 * 9, M + 3 * 9, tid);  // C(3,0), C(0,3), R0, R3
}

// ---------------- single fused kernel ----------------
// blocks 0..63: encoder (4 batch rows, f32x2 packed GEMM) -> spin on g_flag -> contract -> out
// blocks 64,65: adjoint Heisenberg evolution -> g_C -> bump g_flag
__global__ __launch_bounds__(256) void fused_all_kernel(
    const float* __restrict__ x, const float* __restrict__ W1, const float* __restrict__ b1,
    const float* __restrict__ ln_g, const float* __restrict__ ln_b,
    const float* __restrict__ W2, const float* __restrict__ b2,
    const float* __restrict__ shared_w, const float* __restrict__ task_w,
    const float* __restrict__ Wp, const float* __restrict__ bp,
    float* __restrict__ out)
{
    __shared__ __align__(16) float SM[4416];
    int tid = threadIdx.x;
    int lane = tid & 31, warp = tid >> 5;

    if (blockIdx.x < 64) {
        // ======== encoder: 4 batch rows per block, packed f32x2 dual-FMA along k ========
        int b0 = blockIdx.x * 4;
        float* hs = SM;              // [4][256]
        float* red = SM + 1024;      // 32
        float* stat = SM + 1056;     // 4
        float* stat2 = SM + 1060;    // 4
        float* zs = SM + 1064;       // [4][6]
        float* u = SM + 1088;        // [4][3][9] = 108
        float* cred = SM + 1196;     // [8][2]

        // x slices in registers as packed 64-bit k-pairs
        ulonglong2 xq[4][6];
        u64 xt[4];
#pragma unroll
        for (int r = 0; r < 4; r++) {
            const ulonglong2* xg = (const ulonglong2*)(x + (size_t)(b0 + r) * 784);
#pragma unroll
            for (int i = 0; i < 6; i++) xq[r][i] = xg[lane + 32 * i];
            xt[r] = (lane < 8) ? *(const u64*)(x + (size_t)(b0 + r) * 784 + 768 + 2 * lane) : 0ULL;
        }

        // preload W1 row warp*32
        ulonglong2 wq[6];
        u64 wt;
        {
            const ulonglong2* wg = (const ulonglong2*)(W1 + (size_t)(warp * 32) * 784);
#pragma unroll
            for (int i = 0; i < 6; i++) wq[i] = wg[lane + 32 * i];
            wt = (lane < 8) ? *(const u64*)(W1 + (size_t)(warp * 32) * 784 + 768 + 2 * lane) : 0ULL;
        }

        for (int j = 0; j < 32; j++) {
            int row = warp * 32 + j;
            // prefetch next row before consuming current one
            ulonglong2 wn[6];
            u64 wtn = 0ULL;
            if (j < 31) {
                const ulonglong2* wg = (const ulonglong2*)(W1 + (size_t)(row + 1) * 784);
#pragma unroll
                for (int i = 0; i < 6; i++) wn[i] = wg[lane + 32 * i];
                wtn = (lane < 8) ? *(const u64*)(W1 + (size_t)(row + 1) * 784 + 768 + 2 * lane) : 0ULL;
            }
            u64 p0 = 0ULL, p1 = 0ULL, p2 = 0ULL, p3 = 0ULL;
#pragma unroll
            for (int i = 0; i < 6; i++) {
                u64 wx = wq[i].x, wy = wq[i].y;
                p0 = ffma2(wx, xq[0][i].x, p0); p0 = ffma2(wy, xq[0][i].y, p0);
                p1 = ffma2(wx, xq[1][i].x, p1); p1 = ffma2(wy, xq[1][i].y, p1);
                p2 = ffma2(wx, xq[2][i].x, p2); p2 = ffma2(wy, xq[2][i].y, p2);
                p3 = ffma2(wx, xq[3][i].x, p3); p3 = ffma2(wy, xq[3][i].y, p3);
            }
            p0 = ffma2(wt, xt[0], p0);
            p1 = ffma2(wt, xt[1], p1);
            p2 = ffma2(wt, xt[2], p2);
            p3 = ffma2(wt, xt[3], p3);
            float2 f0 = *(float2*)&p0, f1 = *(float2*)&p1, f2 = *(float2*)&p2, f3 = *(float2*)&p3;
            float a0 = f0.x + f0.y, a1 = f1.x + f1.y, a2 = f2.x + f2.y, a3 = f3.x + f3.y;
#pragma unroll
            for (int o = 16; o > 0; o >>= 1) {
                a0 += __shfl_xor_sync(0xffffffffu, a0, o);
                a1 += __shfl_xor_sync(0xffffffffu, a1, o);
                a2 += __shfl_xor_sync(0xffffffffu, a2, o);
                a3 += __shfl_xor_sync(0xffffffffu, a3, o);
            }
            if (lane == 0) {
                float bv = b1[row];
                hs[row] = fmaxf(a0 + bv, 0.f);
                hs[256 + row] = fmaxf(a1 + bv, 0.f);
                hs[512 + row] = fmaxf(a2 + bv, 0.f);
                hs[768 + row] = fmaxf(a3 + bv, 0.f);
            }
#pragma unroll
            for (int i = 0; i < 6; i++) wq[i] = wn[i];
            wt = wtn;
        }
        __syncthreads();

        float h0 = hs[tid], h1 = hs[256 + tid], h2 = hs[512 + tid], h3 = hs[768 + tid];
        {
            float t0 = h0, t1 = h1, t2 = h2, t3 = h3;
#pragma unroll
            for (int o = 16; o > 0; o >>= 1) {
                t0 += __shfl_xor_sync(0xffffffffu, t0, o);
                t1 += __shfl_xor_sync(0xffffffffu, t1, o);
                t2 += __shfl_xor_sync(0xffffffffu, t2, o);
                t3 += __shfl_xor_sync(0xffffffffu, t3, o);
            }
            if (lane == 0) { red[warp] = t0; red[8 + warp] = t1; red[16 + warp] = t2; red[24 + warp] = t3; }
        }
        __syncthreads();
        if (tid < 4) {
            float s = 0.f;
#pragma unroll
            for (int w = 0; w < 8; w++) s += red[tid * 8 + w];
            stat[tid] = s * (1.f / 256.f);
        }
        __syncthreads();
        float d0 = h0 - stat[0], d1 = h1 - stat[1], d2 = h2 - stat[2], d3 = h3 - stat[3];
        {
            float t0 = d0 * d0, t1 = d1 * d1, t2 = d2 * d2, t3 = d3 * d3;
#pragma unroll
            for (int o = 16; o > 0; o >>= 1) {
                t0 += __shfl_xor_sync(0xffffffffu, t0, o);
                t1 += __shfl_xor_sync(0xffffffffu, t1, o);
                t2 += __shfl_xor_sync(0xffffffffu, t2, o);
                t3 += __shfl_xor_sync(0xffffffffu, t3, o);
            }
            if (lane == 0) { red[warp] = t0; red[8 + warp] = t1; red[16 + warp] = t2; red[24 + warp] = t3; }
        }
        __syncthreads();
        if (tid < 4) {
            float s = 0.f;
#pragma unroll
            for (int w = 0; w < 8; w++) s += red[tid * 8 + w];
            stat2[tid] = rsqrtf(s * (1.f / 256.f) + 1e-5f);
        }
        __syncthreads();
        float g = ln_g[tid], be = ln_b[tid];
        hs[tid] = fmaf(d0 * stat2[0], g, be);
        hs[256 + tid] = fmaf(d1 * stat2[1], g, be);
        hs[512 + tid] = fmaf(d2 * stat2[2], g, be);
        hs[768 + tid] = fmaf(d3 * stat2[3], g, be);
        __syncthreads();

        // z = tanh(h @ W2^T + b2) -> smem zs
        for (int p = warp; p < 24; p += 8) {
            int r = p / 6, j = p - r * 6;
            const float* hr = hs + r * 256;
            const float* wj = W2 + j * 256;
            float s = 0.f;
#pragma unroll
            for (int t2_ = lane; t2_ < 256; t2_ += 32) s = fmaf(hr[t2_], wj[t2_], s);
#pragma unroll
            for (int o = 16; o > 0; o >>= 1) s += __shfl_xor_sync(0xffffffffu, s, o);
            if (lane == 0) zs[r * 6 + j] = tanhf(s + b2[j]);
        }

        // ---- wait for adjoint blocks (g_C ready) ----
        if (tid == 0) {
            while (*(volatile int*)&g_flag < 2) { }
        }
        __syncthreads();
        __threadfence();

        // ---- contraction for this block's 4 rows ----
        if (tid < 108) {
            int r = tid / 27, rem = tid % 27, p = rem / 9, ij = rem % 9;
            int i = ij % 3, jj = ij / 3;
            float sa, ca, sb, cb;
            __sincosf(3.14159265358979323846f * zs[r * 6 + 2 * p], &sa, &ca);
            __sincosf(3.14159265358979323846f * zs[r * 6 + 2 * p + 1], &sb, &cb);
            float vi = (i == 0) ? 1.f : ((i == 1) ? L1F * sa : L1F * ca);
            float vj = (jj == 0) ? 1.f : ((jj == 1) ? L1F * sb : L1F * cb);
            u[r * 27 + p * 9 + ij] = vi * vj;
        }
        __syncthreads();

        {
            int r = warp >> 1;                 // warp pair handles row r
            const float* ur = u + r * 27;
            float acc0 = 0.f, acc1 = 0.f;
            for (int s = lane + 32 * (warp & 1); s < 729; s += 64) {
                int i01 = s % 9, q9 = s / 9;
                int i23 = q9 % 9, i45 = q9 / 9;
                float w = ur[i01] * ur[9 + i23] * ur[18 + i45];
                acc0 = fmaf(g_C[s], w, acc0);
                acc1 = fmaf(g_C[729 + s], w, acc1);
            }
#pragma unroll
            for (int o = 16; o > 0; o >>= 1) {
                acc0 += __shfl_xor_sync(0xffffffffu, acc0, o);
                acc1 += __shfl_xor_sync(0xffffffffu, acc1, o);
            }
            if (lane == 0) { cred[warp * 2] = acc0; cred[warp * 2 + 1] = acc1; }
        }
        __syncthreads();
        if (tid < 8) {
            int r = tid >> 1, o = tid & 1;
            out[(b0 + r) * 2 + o] = cred[(2 * r) * 2 + o] + cred[(2 * r + 1) * 2 + o] + bp[o];
        }
        __syncthreads();
        // self-resetting barrier state (last of the 64 encoder blocks resets)
        if (tid == 0) {
            int v = atomicAdd(&g_done, 1);
            if (v == 63) { g_done = 0; g_flag = 0; }
        }
    } else {
        // ======== adjoint Heisenberg evolution for O_op = sum_i Wp[op,i] Z_i ========
        int op = blockIdx.x - 64;
        float* T = SM;            // 4096 Pauli coefficients (swizzled)
        float* MA = SM + 4096;    // 30 x 9 adjoint Bloch matrices (XZY basis)

        if (tid < 30) {
            const float* w = (tid < 18) ? (shared_w + tid * 3) : (task_w + (tid - 18) * 3);
            float a = -w[0], b = -w[1], gg = -w[2];
            float ca, sa, cb, sb, cg, sg;
            sincosf(a, &sa, &ca);
            sincosf(b, &sb, &cb);
            sincosf(gg, &sg, &cg);
            float A00 = ca * cb * cg - sa * sg;
            float A01 = -ca * cb * sg - sa * cg;
            float A02 = ca * sb;
            float A10 = sa * cb * cg + ca * sg;
            float A11 = -sa * cb * sg + ca * cg;
            float A12 = sa * sb;
            float A20 = -sb * cg;
            float A21 = sb * sg;
            float A22 = cb;
            float* M = MA + tid * 9;   // order (X,Z,Y) = XYZ rows/cols (0,2,1)
            M[0] = A00; M[1] = A02; M[2] = A01;
            M[3] = A20; M[4] = A22; M[5] = A21;
            M[6] = A10; M[7] = A12; M[8] = A11;
        }
#pragma unroll
        for (int k = 0; k < 16; k++) T[tid + 256 * k] = 0.f;
        __syncthreads();
        if (tid < 6) T[SW(2 << (2 * tid))] = L1F * Wp[op * NQ + tid];

        for (int it = 0; it < 2; it++) {
            layerR2(T, MA + (it ? 6 : 24) * 9, tid);
            layerR1(T, MA + (it ? 0 : 18) * 9, tid);
            if (it == 0) layerR3(T, MA + 12 * 9, tid);
        }
        __syncthreads();
        // write Y-free strings compacted to base-3 index
#pragma unroll
        for (int k = 0; k < 16; k++) {
            int s = tid + 256 * k;
            if ((s & (s >> 1) & 0x555) == 0) {
                int s3 = 0;
#pragma unroll
                for (int q = 5; q >= 0; q--) s3 = s3 * 3 + ((s >> (2 * q)) & 3);
                g_C[op * 729 + s3] = T[SW(s)];
            }
        }
        __threadfence();
        __syncthreads();
        if (tid == 0) atomicAdd(&g_flag, 1);
    }
}

extern "C" void kernel_launch(void* const* d_in, const int* in_sizes, int n_in,
                              void* d_out, int out_size) {
    const float* x        = (const float*)d_in[0];
    const float* W1       = (const float*)d_in[1];
    const float* b1       = (const float*)d_in[2];
    const float* ln_g     = (const float*)d_in[3];
    const float* ln_b     = (const float*)d_in[4];
    const float* W2       = (const float*)d_in[5];
    const float* b2       = (const float*)d_in[6];
    const float* shared_w = (const float*)d_in[7];
    const float* task_w   = (const float*)d_in[8];
    const float* Wp       = (const float*)d_in[9];
    const float* bp       = (const float*)d_in[10];
    float* out = (float*)d_out;

    fused_all_kernel<<<66, 256>>>(x, W1, b1, ln_g, ln_b, W2, b2,
                                  shared_w, task_w, Wp, bp, out);
}

// round 14
// speedup vs baseline: 1.3358x; 1.3339x over previous
#include <cuda_runtime.h>
#include <cuda_bf16.h>
#include <cstdint>

#define NQ 6
#define BATCH 256

__device__ float g_C[2 * 729];
__device__ int g_flag;   // adjoint-done counter (0 -> 2), reset each launch
__device__ int g_done;   // encoder-done counter (0 -> 128), reset each launch

#define L1F 0.99866666666666666f   /* 1 - 4*0.001/3 */
#define L12F 0.98535111111111111f  /* L1 * (1 - 4*0.01/3) */

// bank-conflict swizzle for the 4096-entry Pauli table (GF(2)-linear)
#define SW(i) ((i) ^ (((i) >> 5) & 31))

typedef unsigned long long u64;

// packed dual-fp32 FMA (sm_100+): d = a*b + c elementwise on two lanes
__device__ __forceinline__ u64 ffma2(u64 a, u64 b, u64 c) {
    u64 d;
    asm("fma.rn.f32x2 %0, %1, %2, %3;" : "=l"(d) : "l"(a), "l"(b), "l"(c));
    return d;
}

// ---------- adjoint (Heisenberg) Pauli-basis sweeps; symplectic digits I=0,X=1,Z=2,Y=3 ----------

template<bool CTRL_A>
__device__ __forceinline__ void cnot_regs(float v[4][4]) {
    float w[4][4];
#pragma unroll
    for (int da = 0; da < 4; da++)
#pragma unroll
        for (int db = 0; db < 4; db++) {
            int dc = CTRL_A ? da : db;
            int dt = CTRL_A ? db : da;
            int xc = dc & 1, zc = dc >> 1, xt = dt & 1, zt = dt >> 1;
            int ndc = xc | ((zc ^ zt) << 1);
            int ndt = (xt ^ xc) | (zt << 1);
            int na = CTRL_A ? ndc : ndt;
            int nb = CTRL_A ? ndt : ndc;
            int neg = xc & zt & (1 ^ (zc ^ xt));
            float val = v[da][db];
            w[na][nb] = neg ? -val : val;
        }
#pragma unroll
    for (int i = 0; i < 4; i++)
#pragma unroll
        for (int j = 0; j < 4; j++) v[i][j] = w[i][j];
}

// Byte offsets: 4*SW(base+off) = tb ^ (4*SW(off)), tb = 4*SW(base); integer-space XOR exact.
// Only threads with act==true touch the table; ALL threads hit the barrier.
template<int A, int B, bool CTRL_B1, bool DOUBLE, bool DEPOL, bool RA, bool RB>
__device__ __forceinline__ void sweep(float* T, const float* Ma, const float* Mb, int tid, bool act) {
    __syncthreads();
    constexpr int lo = 2 * A, hi = 2 * B;
    int m1 = (1 << lo) - 1;
    int t1 = ((tid & ~m1) << 2) | (tid & m1);
    int m2 = (1 << hi) - 1;
    int base = ((t1 & ~m2) << 2) | (t1 & m2);
    int tb = 4 * SW(base);
    char* Tc = (char*)T;

    if (!act) return;   // inactive warps: barrier only (uniform per warp)

    float v[4][4];
#pragma unroll
    for (int i = 0; i < 4; i++)
#pragma unroll
        for (int j = 0; j < 4; j++) {
            int off = (i << lo) | (j << hi);
            int c4 = 4 * SW(off);
            v[i][j] = *(const float*)(Tc + (tb ^ c4));
        }

    if (DEPOL) {
        float fixed = 1.f;
#pragma unroll
        for (int q = 0; q < 6; q++) {
            if (q == A || q == B) continue;
            if ((base >> (2 * q)) & 3) fixed *= (q == 5 ? L1F : L12F);
        }
        const float la = (A == 5 ? L1F : L12F), lb = (B == 5 ? L1F : L12F);
#pragma unroll
        for (int i = 0; i < 4; i++)
#pragma unroll
            for (int j = 0; j < 4; j++) {
                float f = fixed;
                if (i) f *= la;
                if (j) f *= lb;
                v[i][j] *= f;
            }
    }

    cnot_regs<!CTRL_B1>(v);
    if (DOUBLE) cnot_regs<CTRL_B1>(v);

    if (RA) {
        float a0 = Ma[0], a1 = Ma[1], a2 = Ma[2], a3 = Ma[3], a4 = Ma[4];
        float a5 = Ma[5], a6 = Ma[6], a7 = Ma[7], a8 = Ma[8];
#pragma unroll
        for (int j = 0; j < 4; j++) {
            float x = v[1][j], z = v[2][j], y = v[3][j];
            v[1][j] = fmaf(a0, x, fmaf(a1, z, a2 * y));
            v[2][j] = fmaf(a3, x, fmaf(a4, z, a5 * y));
            v[3][j] = fmaf(a6, x, fmaf(a7, z, a8 * y));
        }
    }
    if (RB) {
        float b0 = Mb[0], b1 = Mb[1], b2 = Mb[2], b3 = Mb[3], b4 = Mb[4];
        float b5 = Mb[5], b6 = Mb[6], b7 = Mb[7], b8 = Mb[8];
#pragma unroll
        for (int i = 0; i < 4; i++) {
            float x = v[i][1], z = v[i][2], y = v[i][3];
            v[i][1] = fmaf(b0, x, fmaf(b1, z, b2 * y));
            v[i][2] = fmaf(b3, x, fmaf(b4, z, b5 * y));
            v[i][3] = fmaf(b6, x, fmaf(b7, z, b8 * y));
        }
    }

#pragma unroll
    for (int i = 0; i < 4; i++)
#pragma unroll
        for (int j = 0; j < 4; j++) {
            int off = (i << lo) | (j << hi);
            int c4 = 4 * SW(off);
            *(float*)(Tc + (tb ^ c4)) = v[i][j];
        }
}

__device__ __forceinline__ void layerR1(float* T, const float* M, int tid, bool act) {
    sweep<0, 5, true,  false, false, false, false>(T, M, M, tid, act);                  // C(5,0)
    sweep<4, 5, false, false, false, false, true >(T, M, M + 5 * 9, tid, act);          // C(4,5), R5
    sweep<3, 4, false, false, false, false, true >(T, M, M + 4 * 9, tid, act);          // C(3,4), R4
    sweep<2, 3, false, false, false, false, true >(T, M, M + 3 * 9, tid, act);          // C(2,3), R3
    sweep<1, 2, false, false, false, false, true >(T, M, M + 2 * 9, tid, act);          // C(1,2), R2
    sweep<0, 1, false, false, false, true,  true >(T, M + 0 * 9, M + 1 * 9, tid, act);  // C(0,1), R0, R1
}

__device__ __forceinline__ void layerR2(float* T, const float* M, int tid, bool act) {
    sweep<1, 5, true,  false, false, false, false>(T, M, M, tid, act);                  // C(5,1)
    sweep<3, 5, false, false, false, false, true >(T, M, M + 5 * 9, tid, act);          // C(3,5), R5
    sweep<1, 3, false, false, false, true,  true >(T, M + 1 * 9, M + 3 * 9, tid, act);  // C(1,3), R1, R3
    sweep<0, 4, true,  false, false, false, false>(T, M, M, tid, act);                  // C(4,0)
    sweep<2, 4, false, false, false, false, true >(T, M, M + 4 * 9, tid, act);          // C(2,4), R4
    sweep<0, 2, false, false, false, true,  true >(T, M + 0 * 9, M + 2 * 9, tid, act);  // C(0,2), R0, R2
}

__device__ __forceinline__ void layerR3(float* T, const float* M, int tid, bool act) {
    sweep<2, 5, true, true, true,  true, true>(T, M + 2 * 9, M + 5 * 9, tid, act);  // depol, C(5,2), C(2,5), R2, R5
    sweep<1, 4, true, true, false, true, true>(T, M + 1 * 9, M + 4 * 9, tid, act);  // C(4,1), C(1,4), R1, R4
    sweep<0, 3, true, true, false, true, true>(T, M + 0 * 9, M + 3 * 9, tid, act);  // C(3,0), C(0,3), R0, R3
}

// ---------------- single fused kernel, 512 threads/block ----------------
// blocks 0..127: encoder (2 batch rows) -> spin on g_flag -> contract -> out
// blocks 128,129: adjoint Heisenberg evolution (256 active threads) -> g_C -> bump g_flag
__global__ __launch_bounds__(512, 1) void fused_all_kernel(
    const float* __restrict__ x, const float* __restrict__ W1, const float* __restrict__ b1,
    const float* __restrict__ ln_g, const float* __restrict__ ln_b,
    const float* __restrict__ W2, const float* __restrict__ b2,
    const float* __restrict__ shared_w, const float* __restrict__ task_w,
    const float* __restrict__ Wp, const float* __restrict__ bp,
    float* __restrict__ out)
{
    __shared__ __align__(16) float SM[4416];
    int tid = threadIdx.x;
    int lane = tid & 31, warp = tid >> 5;

    if (blockIdx.x < 128) {
        // ======== encoder: 2 batch rows per block, 16 warps, coalesced W1 ========
        int b0 = blockIdx.x * 2;
        float* hs = SM;              // [2][256]
        float* red = SM + 512;       // 16
        float* stat = SM + 528;      // 2
        float* stat2 = SM + 530;     // 2
        float* zs = SM + 532;        // [2][6]
        float* u = SM + 544;         // [2][3][9] = 54
        float* cred = SM + 600;      // [16][2]

        // x slices in registers as packed 64-bit k-pairs
        ulonglong2 xq[2][6];
        u64 xt[2];
#pragma unroll
        for (int r = 0; r < 2; r++) {
            const ulonglong2* xg = (const ulonglong2*)(x + (size_t)(b0 + r) * 784);
#pragma unroll
            for (int i = 0; i < 6; i++) xq[r][i] = xg[lane + 32 * i];
            xt[r] = (lane < 8) ? *(const u64*)(x + (size_t)(b0 + r) * 784 + 768 + 2 * lane) : 0ULL;
        }

        // warp w computes output rows w*16 .. w*16+15
        for (int j = 0; j < 16; j++) {
            int row = warp * 16 + j;
            const ulonglong2* wg = (const ulonglong2*)(W1 + (size_t)row * 784);
            ulonglong2 wq[6];
#pragma unroll
            for (int i = 0; i < 6; i++) wq[i] = wg[lane + 32 * i];
            u64 wt = (lane < 8) ? *(const u64*)(W1 + (size_t)row * 784 + 768 + 2 * lane) : 0ULL;
            u64 p0 = 0ULL, p1 = 0ULL;
#pragma unroll
            for (int i = 0; i < 6; i++) {
                u64 wx = wq[i].x, wy = wq[i].y;
                p0 = ffma2(wx, xq[0][i].x, p0); p0 = ffma2(wy, xq[0][i].y, p0);
                p1 = ffma2(wx, xq[1][i].x, p1); p1 = ffma2(wy, xq[1][i].y, p1);
            }
            p0 = ffma2(wt, xt[0], p0);
            p1 = ffma2(wt, xt[1], p1);
            float2 f0 = *(float2*)&p0, f1 = *(float2*)&p1;
            float a0 = f0.x + f0.y, a1 = f1.x + f1.y;
#pragma unroll
            for (int o = 16; o > 0; o >>= 1) {
                a0 += __shfl_xor_sync(0xffffffffu, a0, o);
                a1 += __shfl_xor_sync(0xffffffffu, a1, o);
            }
            if (lane == 0) {
                float bv = b1[row];
                hs[row] = fmaxf(a0 + bv, 0.f);
                hs[256 + row] = fmaxf(a1 + bv, 0.f);
            }
        }
        __syncthreads();

        // ---- LayerNorm over 256 elements (threads 0..255 active) ----
        float h0 = 0.f, h1 = 0.f;
        if (tid < 256) {
            h0 = hs[tid];
            h1 = hs[256 + tid];
            float t0 = h0, t1 = h1;
#pragma unroll
            for (int o = 16; o > 0; o >>= 1) {
                t0 += __shfl_xor_sync(0xffffffffu, t0, o);
                t1 += __shfl_xor_sync(0xffffffffu, t1, o);
            }
            if (lane == 0) { red[warp] = t0; red[8 + warp] = t1; }
        }
        __syncthreads();
        if (tid < 2) {
            float s = 0.f;
#pragma unroll
            for (int w = 0; w < 8; w++) s += red[tid * 8 + w];
            stat[tid] = s * (1.f / 256.f);
        }
        __syncthreads();
        float d0 = h0 - stat[0], d1 = h1 - stat[1];
        if (tid < 256) {
            float t0 = d0 * d0, t1 = d1 * d1;
#pragma unroll
            for (int o = 16; o > 0; o >>= 1) {
                t0 += __shfl_xor_sync(0xffffffffu, t0, o);
                t1 += __shfl_xor_sync(0xffffffffu, t1, o);
            }
            if (lane == 0) { red[warp] = t0; red[8 + warp] = t1; }
        }
        __syncthreads();
        if (tid < 2) {
            float s = 0.f;
#pragma unroll
            for (int w = 0; w < 8; w++) s += red[tid * 8 + w];
            stat2[tid] = rsqrtf(s * (1.f / 256.f) + 1e-5f);
        }
        __syncthreads();
        if (tid < 256) {
            float g = ln_g[tid], be = ln_b[tid];
            hs[tid] = fmaf(d0 * stat2[0], g, be);
            hs[256 + tid] = fmaf(d1 * stat2[1], g, be);
        }
        __syncthreads();

        // z = tanh(h @ W2^T + b2): 12 (row, j) pairs over warps 0..11
        if (warp < 12) {
            int r = warp / 6, j = warp - r * 6;
            const float* hr = hs + r * 256;
            const float* wj = W2 + j * 256;
            float s = 0.f;
#pragma unroll
            for (int t2_ = lane; t2_ < 256; t2_ += 32) s = fmaf(hr[t2_], wj[t2_], s);
#pragma unroll
            for (int o = 16; o > 0; o >>= 1) s += __shfl_xor_sync(0xffffffffu, s, o);
            if (lane == 0) zs[r * 6 + j] = tanhf(s + b2[j]);
        }

        // ---- wait for adjoint blocks (g_C ready) ----
        if (tid == 0) {
            while (*(volatile int*)&g_flag < 2) { }
        }
        __syncthreads();
        __threadfence();

        // ---- contraction for this block's 2 rows ----
        if (tid < 54) {
            int r = tid / 27, rem = tid % 27, p = rem / 9, ij = rem % 9;
            int i = ij % 3, jj = ij / 3;
            float sa, ca, sb, cb;
            __sincosf(3.14159265358979323846f * zs[r * 6 + 2 * p], &sa, &ca);
            __sincosf(3.14159265358979323846f * zs[r * 6 + 2 * p + 1], &sb, &cb);
            float vi = (i == 0) ? 1.f : ((i == 1) ? L1F * sa : L1F * ca);
            float vj = (jj == 0) ? 1.f : ((jj == 1) ? L1F * sb : L1F * cb);
            u[r * 27 + p * 9 + ij] = vi * vj;
        }
        __syncthreads();

        {
            int r = warp >> 3;                 // 8 warps per row
            const float* ur = u + r * 27;
            float acc0 = 0.f, acc1 = 0.f;
            for (int s = lane + 32 * (warp & 7); s < 729; s += 256) {
                int i01 = s % 9, q9 = s / 9;
                int i23 = q9 % 9, i45 = q9 / 9;
                float w = ur[i01] * ur[9 + i23] * ur[18 + i45];
                acc0 = fmaf(g_C[s], w, acc0);
                acc1 = fmaf(g_C[729 + s], w, acc1);
            }
#pragma unroll
            for (int o = 16; o > 0; o >>= 1) {
                acc0 += __shfl_xor_sync(0xffffffffu, acc0, o);
                acc1 += __shfl_xor_sync(0xffffffffu, acc1, o);
            }
            if (lane == 0) { cred[warp * 2] = acc0; cred[warp * 2 + 1] = acc1; }
        }
        __syncthreads();
        if (tid < 4) {
            int r = tid >> 1, o = tid & 1;
            float s = bp[o];
#pragma unroll
            for (int w = 0; w < 8; w++) s += cred[(8 * r + w) * 2 + o];
            out[(b0 + r) * 2 + o] = s;
        }
        __syncthreads();
        // self-resetting barrier state (last of the 128 encoder blocks resets)
        if (tid == 0) {
            int v = atomicAdd(&g_done, 1);
            if (v == 127) { g_done = 0; g_flag = 0; }
        }
    } else {
        // ======== adjoint Heisenberg evolution for O_op = sum_i Wp[op,i] Z_i ========
        int op = blockIdx.x - 128;
        bool act = tid < 256;
        float* T = SM;            // 4096 Pauli coefficients (swizzled)
        float* MA = SM + 4096;    // 30 x 9 adjoint Bloch matrices (XZY basis)

        if (tid < 30) {
            const float* w = (tid < 18) ? (shared_w + tid * 3) : (task_w + (tid - 18) * 3);
            float a = -w[0], b = -w[1], gg = -w[2];
            float ca, sa, cb, sb, cg, sg;
            sincosf(a, &sa, &ca);
            sincosf(b, &sb, &cb);
            sincosf(gg, &sg, &cg);
            float A00 = ca * cb * cg - sa * sg;
            float A01 = -ca * cb * sg - sa * cg;
            float A02 = ca * sb;
            float A10 = sa * cb * cg + ca * sg;
            float A11 = -sa * cb * sg + ca * cg;
            float A12 = sa * sb;
            float A20 = -sb * cg;
            float A21 = sb * sg;
            float A22 = cb;
            float* M = MA + tid * 9;   // order (X,Z,Y) = XYZ rows/cols (0,2,1)
            M[0] = A00; M[1] = A02; M[2] = A01;
            M[3] = A20; M[4] = A22; M[5] = A21;
            M[6] = A10; M[7] = A12; M[8] = A11;
        }
        if (act) {
#pragma unroll
            for (int k = 0; k < 16; k++) T[tid + 256 * k] = 0.f;
        }
        __syncthreads();
        if (tid < 6) T[SW(2 << (2 * tid))] = L1F * Wp[op * NQ + tid];

        for (int it = 0; it < 2; it++) {
            layerR2(T, MA + (it ? 6 : 24) * 9, tid, act);
            layerR1(T, MA + (it ? 0 : 18) * 9, tid, act);
            if (it == 0) layerR3(T, MA + 12 * 9, tid, act);
        }
        __syncthreads();
        // write Y-free strings compacted to base-3 index
        if (act) {
#pragma unroll
            for (int k = 0; k < 16; k++) {
                int s = tid + 256 * k;
                if ((s & (s >> 1) & 0x555) == 0) {
                    int s3 = 0;
#pragma unroll
                    for (int q = 5; q >= 0; q--) s3 = s3 * 3 + ((s >> (2 * q)) & 3);
                    g_C[op * 729 + s3] = T[SW(s)];
                }
            }
        }
        __threadfence();
        __syncthreads();
        if (tid == 0) atomicAdd(&g_flag, 1);
    }
}

extern "C" void kernel_launch(void* const* d_in, const int* in_sizes, int n_in,
                              void* d_out, int out_size) {
    const float* x        = (const float*)d_in[0];
    const float* W1       = (const float*)d_in[1];
    const float* b1       = (const float*)d_in[2];
    const float* ln_g     = (const float*)d_in[3];
    const float* ln_b     = (const float*)d_in[4];
    const float* W2       = (const float*)d_in[5];
    const float* b2       = (const float*)d_in[6];
    const float* shared_w = (const float*)d_in[7];
    const float* task_w   = (const float*)d_in[8];
    const float* Wp       = (const float*)d_in[9];
    const float* bp       = (const float*)d_in[10];
    float* out = (float*)d_out;

    fused_all_kernel<<<130, 512>>>(x, W1, b1, ln_g, ln_b, W2, b2,
                                   shared_w, task_w, Wp, bp, out);
}